// round 1
// baseline (speedup 1.0000x reference)
#include <cuda_runtime.h>
#include <math.h>

#define N_PTS   8192
#define D_DIM   8
#define K_DIM   64
#define Q_DIM   16
#define KQ      1024            // K*Q
#define TWO_PI  6.283185307179586f

#define EPHI_SZ (N_PTS * KQ)    // 8388608
#define G_SZ    (KQ * KQ)       // 1048576
// d_out layout: [E_phi (N,KQ) | G (KQ,KQ) | E_cos_sq (N,KQ)]

// -------- device scratch (allocation-free rule: __device__ globals) --------
__device__ float g_Ew[D_DIM * KQ];   // E_w[d,kq]
__device__ float g_C [D_DIM * KQ];   // std_p[d,q]^2 * var_sigma_w[d,kq]
__device__ float g_zs[D_DIM * KQ];   // 2*pi*z[d,kq]
__device__ float g_diag[KQ];         // sum_n E_cos_sq[n,kq]

// ---------------------------------------------------------------------------
// Kernel 0: precompute per-(d,kq) coefficient tables (8192 elements)
// ---------------------------------------------------------------------------
__global__ void precompute_kernel(const float* __restrict__ z,
                                  const float* __restrict__ mu,
                                  const float* __restrict__ stdv,
                                  const float* __restrict__ var_mu_w,
                                  const float* __restrict__ var_sigma_w)
{
    int idx = blockIdx.x * blockDim.x + threadIdx.x;
    if (idx >= D_DIM * KQ) return;
    int d  = idx >> 10;          // / KQ
    int kq = idx & (KQ - 1);
    int q  = kq & (Q_DIM - 1);

    float mean_p = 1.0f / (mu[d * Q_DIM + q] + 1e-8f);
    float std_p  = 1.0f / (TWO_PI * stdv[d * Q_DIM + q] + 1e-8f);

    g_Ew[idx] = mean_p + std_p * var_mu_w[idx];
    g_C [idx] = std_p * std_p * var_sigma_w[idx];
    g_zs[idx] = TWO_PI * z[idx];
}

// ---------------------------------------------------------------------------
// Kernel 1: E_phi and E_cos_sq.
// grid = (4, 256), block = 256. blockIdx.x selects 256-wide kq slab,
// blockIdx.y selects 32 consecutive n rows. Each thread owns ONE kq column
// (coefficients live in registers) and iterates the 32 rows.
// ---------------------------------------------------------------------------
__global__ void ephi_kernel(const float* __restrict__ X,
                            const float* __restrict__ weight,
                            const float* __restrict__ alpha,
                            float* __restrict__ out)
{
    const int tid = threadIdx.x;
    const int kq  = blockIdx.x * 256 + tid;
    const int n0  = blockIdx.y * 32;

    __shared__ float Xs[32 * D_DIM];           // 256 floats, pre-scaled by 2*pi
    Xs[tid] = TWO_PI * X[n0 * D_DIM + tid];
    __syncthreads();

    float ew[D_DIM], cc[D_DIM], zz[D_DIM];
#pragma unroll
    for (int d = 0; d < D_DIM; ++d) {
        ew[d] = g_Ew[d * KQ + kq];
        cc[d] = g_C [d * KQ + kq];
        zz[d] = g_zs[d * KQ + kq];
    }
    const int   q    = kq & (Q_DIM - 1);
    const float a    = alpha[kq];
    const float coef = 2.0f * weight[q] * (1.0f / (float)K_DIM);  // 2w/K
    const float sq   = sqrtf(coef);

    float* __restrict__ outE = out;                       // E_phi
    float* __restrict__ outC = out + EPHI_SZ + G_SZ;      // E_cos_sq

#pragma unroll 4
    for (int r = 0; r < 32; ++r) {
        float phase = 0.0f, s = 0.0f;
#pragma unroll
        for (int d = 0; d < D_DIM; ++d) {
            float xb = Xs[r * D_DIM + d] - zz[d];          // 2*pi*(X - z)
            phase = fmaf(xb, ew[d], phase);
            s     = fmaf(cc[d], xb * xb, s);
        }
        float cw    = cosf(a + phase);
        float decay = expf(-0.5f * s);

        const int n = n0 + r;
        outE[n * KQ + kq] = sq * decay * cw;

        float d2  = decay * decay;
        float d4  = d2 * d2;
        float c2w = 2.0f * cw * cw - 1.0f;                 // cos(2a+2phase)
        outC[n * KQ + kq] = coef * (0.5f + 0.5f * d4 * c2w);
    }
}

// ---------------------------------------------------------------------------
// Kernel 2: diag[kq] = sum_n E_cos_sq[n,kq].
// grid = 32 blocks of 256 threads; block b handles 32 columns. Threads are
// (group g = tid/32, col c = tid%32); warp reads 32 consecutive columns.
// ---------------------------------------------------------------------------
__global__ void diag_kernel(const float* __restrict__ out)
{
    const float* __restrict__ ecs = out + EPHI_SZ + G_SZ;
    const int tid  = threadIdx.x;
    const int base = blockIdx.x * 32;
    const int c    = tid & 31;
    const int g    = tid >> 5;

    float s = 0.0f;
    for (int n = g; n < N_PTS; n += 8)
        s += ecs[n * KQ + base + c];

    __shared__ float red[256];
    red[tid] = s;
    __syncthreads();
    if (tid < 32) {
        float tot = 0.0f;
#pragma unroll
        for (int gg = 0; gg < 8; ++gg) tot += red[gg * 32 + tid];
        g_diag[base + tid] = tot;
    }
}

// ---------------------------------------------------------------------------
// Kernel 3: G = E_phi^T @ E_phi (symmetric SYRK, upper-triangular tiles).
// 64x64 tile, 256 threads (16x16), 4x4 microtile, k-tile = 32.
// grid = 136 blocks (16*17/2 upper tiles). Mirrors each tile to lower half.
// ---------------------------------------------------------------------------
__global__ void syrk_kernel(float* __restrict__ out)
{
    const float* __restrict__ A = out;              // E_phi [N, KQ] row-major
    float* __restrict__ G = out + EPHI_SZ;

    // map linear block -> upper-triangular tile (ti <= tj), 16 tiles per dim
    int b = blockIdx.x;
    int ti = 0, rem = b;
    while (rem >= 16 - ti) { rem -= 16 - ti; ++ti; }
    int tj = ti + rem;

    const int i0 = ti * 64;
    const int j0 = tj * 64;

    __shared__ float As[32][64];
    __shared__ float Bs[32][64];

    const int tid = threadIdx.x;
    const int tx  = tid & 15;
    const int ty  = tid >> 4;

    float acc[4][4];
#pragma unroll
    for (int u = 0; u < 4; ++u)
#pragma unroll
        for (int v = 0; v < 4; ++v) acc[u][v] = 0.0f;

    for (int k0 = 0; k0 < N_PTS; k0 += 32) {
#pragma unroll
        for (int l = 0; l < 8; ++l) {
            int idx = tid + l * 256;
            int r = idx >> 6;
            int c = idx & 63;
            As[r][c] = A[(k0 + r) * KQ + i0 + c];
            Bs[r][c] = A[(k0 + r) * KQ + j0 + c];
        }
        __syncthreads();

#pragma unroll
        for (int kk = 0; kk < 32; ++kk) {
            float4 av = *reinterpret_cast<const float4*>(&As[kk][ty * 4]);
            float4 bv = *reinterpret_cast<const float4*>(&Bs[kk][tx * 4]);
            float aa[4] = {av.x, av.y, av.z, av.w};
            float bb[4] = {bv.x, bv.y, bv.z, bv.w};
#pragma unroll
            for (int u = 0; u < 4; ++u)
#pragma unroll
                for (int v = 0; v < 4; ++v)
                    acc[u][v] = fmaf(aa[u], bb[v], acc[u][v]);
        }
        __syncthreads();
    }

#pragma unroll
    for (int u = 0; u < 4; ++u) {
#pragma unroll
        for (int v = 0; v < 4; ++v) {
            int gi = i0 + ty * 4 + u;
            int gj = j0 + tx * 4 + v;
            G[gi * KQ + gj] = acc[u][v];
            G[gj * KQ + gi] = acc[u][v];   // mirror (benign bitwise-equal race on diag tile)
        }
    }
}

// ---------------------------------------------------------------------------
// Kernel 4: splice in the corrected diagonal.
// ---------------------------------------------------------------------------
__global__ void diagfix_kernel(float* __restrict__ out)
{
    int i = blockIdx.x * blockDim.x + threadIdx.x;
    if (i < KQ) out[EPHI_SZ + i * KQ + i] = g_diag[i];
}

// ---------------------------------------------------------------------------
extern "C" void kernel_launch(void* const* d_in, const int* in_sizes, int n_in,
                              void* d_out, int out_size)
{
    const float* X           = (const float*)d_in[0];  // [8192, 8]
    const float* z           = (const float*)d_in[1];  // [8, 64, 16]
    const float* weight      = (const float*)d_in[2];  // [16]
    const float* mu          = (const float*)d_in[3];  // [8, 16]
    const float* stdv        = (const float*)d_in[4];  // [8, 16]
    const float* alpha       = (const float*)d_in[5];  // [64, 16]
    const float* var_mu_w    = (const float*)d_in[6];  // [8, 64, 16]
    const float* var_sigma_w = (const float*)d_in[7];  // [8, 64, 16]
    float* out = (float*)d_out;

    precompute_kernel<<<32, 256>>>(z, mu, stdv, var_mu_w, var_sigma_w);

    dim3 egrid(KQ / 256, N_PTS / 32);
    ephi_kernel<<<egrid, 256>>>(X, weight, alpha, out);

    diag_kernel<<<KQ / 32, 256>>>(out);

    syrk_kernel<<<136, 256>>>(out);

    diagfix_kernel<<<4, 256>>>(out);
}

// round 3
// speedup vs baseline: 2.3592x; 2.3592x over previous
#include <cuda_runtime.h>
#include <cuda_bf16.h>
#include <math.h>
#include <stdint.h>

#define N_PTS   8192
#define D_DIM   8
#define K_DIM   64
#define Q_DIM   16
#define KQ      1024
#define TWO_PI  6.283185307179586f

#define EPHI_SZ (N_PTS * KQ)    // 8388608
#define G_SZ    (KQ * KQ)       // 1048576
// d_out layout: [E_phi (N,KQ) | G (KQ,KQ) | E_cos_sq (N,KQ)]

// -------- device scratch --------
__device__ float g_Ew[D_DIM * KQ];
__device__ float g_C [D_DIM * KQ];
__device__ float g_zs[D_DIM * KQ];
__device__ float g_diag[KQ];
// transposed split E_phi: [KQ][N_PTS] bf16, n contiguous
__device__ __nv_bfloat16 g_hi[(size_t)KQ * N_PTS];
__device__ __nv_bfloat16 g_lo[(size_t)KQ * N_PTS];

// ---------------------------------------------------------------------------
// helpers (sm_80-level PTX only: cp.async, ldmatrix, mma.sync)
// ---------------------------------------------------------------------------
__device__ __forceinline__ uint32_t smem_u32(const void* p) {
    uint32_t a;
    asm("{ .reg .u64 t; cvta.to.shared.u64 t, %1; cvt.u32.u64 %0, t; }"
        : "=r"(a) : "l"(p));
    return a;
}
__device__ __forceinline__ void cp16(uint32_t dst, const void* src) {
    asm volatile("cp.async.cg.shared.global [%0], [%1], 16;"
                 :: "r"(dst), "l"(src));
}
__device__ __forceinline__ void cp_commit() {
    asm volatile("cp.async.commit_group;" ::: "memory");
}
template <int N>
__device__ __forceinline__ void cp_wait() {
    asm volatile("cp.async.wait_group %0;" :: "n"(N) : "memory");
}
__device__ __forceinline__ void ldsm4(uint32_t* r, uint32_t addr) {
    asm volatile("ldmatrix.sync.aligned.m8n8.x4.shared.b16 {%0,%1,%2,%3}, [%4];"
                 : "=r"(r[0]), "=r"(r[1]), "=r"(r[2]), "=r"(r[3]) : "r"(addr));
}
__device__ __forceinline__ void mma_bf16(float* c, const uint32_t* a,
                                         uint32_t b0, uint32_t b1) {
    asm volatile(
        "mma.sync.aligned.m16n8k16.row.col.f32.bf16.bf16.f32 "
        "{%0,%1,%2,%3}, {%4,%5,%6,%7}, {%8,%9}, {%0,%1,%2,%3};"
        : "+f"(c[0]), "+f"(c[1]), "+f"(c[2]), "+f"(c[3])
        : "r"(a[0]), "r"(a[1]), "r"(a[2]), "r"(a[3]), "r"(b0), "r"(b1));
}

// ---------------------------------------------------------------------------
// Kernel 0: precompute coefficient tables
// ---------------------------------------------------------------------------
__global__ void precompute_kernel(const float* __restrict__ z,
                                  const float* __restrict__ mu,
                                  const float* __restrict__ stdv,
                                  const float* __restrict__ var_mu_w,
                                  const float* __restrict__ var_sigma_w)
{
    int idx = blockIdx.x * blockDim.x + threadIdx.x;
    if (idx >= D_DIM * KQ) return;
    int d  = idx >> 10;
    int kq = idx & (KQ - 1);
    int q  = kq & (Q_DIM - 1);

    float mean_p = 1.0f / (mu[d * Q_DIM + q] + 1e-8f);
    float std_p  = 1.0f / (TWO_PI * stdv[d * Q_DIM + q] + 1e-8f);

    g_Ew[idx] = mean_p + std_p * var_mu_w[idx];
    g_C [idx] = std_p * std_p * var_sigma_w[idx];
    g_zs[idx] = TWO_PI * z[idx];
}

// ---------------------------------------------------------------------------
// Kernel 1: E_phi and E_cos_sq
// ---------------------------------------------------------------------------
__global__ void ephi_kernel(const float* __restrict__ X,
                            const float* __restrict__ weight,
                            const float* __restrict__ alpha,
                            float* __restrict__ out)
{
    const int tid = threadIdx.x;
    const int kq  = blockIdx.x * 256 + tid;
    const int n0  = blockIdx.y * 32;

    __shared__ float Xs[32 * D_DIM];
    Xs[tid] = TWO_PI * X[n0 * D_DIM + tid];
    __syncthreads();

    float ew[D_DIM], cc[D_DIM], zz[D_DIM];
#pragma unroll
    for (int d = 0; d < D_DIM; ++d) {
        ew[d] = g_Ew[d * KQ + kq];
        cc[d] = g_C [d * KQ + kq];
        zz[d] = g_zs[d * KQ + kq];
    }
    const int   q    = kq & (Q_DIM - 1);
    const float a    = alpha[kq];
    const float coef = 2.0f * weight[q] * (1.0f / (float)K_DIM);
    const float sq   = sqrtf(coef);

    float* __restrict__ outE = out;
    float* __restrict__ outC = out + EPHI_SZ + G_SZ;

#pragma unroll 4
    for (int r = 0; r < 32; ++r) {
        float phase = 0.0f, s = 0.0f;
#pragma unroll
        for (int d = 0; d < D_DIM; ++d) {
            float xb = Xs[r * D_DIM + d] - zz[d];
            phase = fmaf(xb, ew[d], phase);
            s     = fmaf(cc[d], xb * xb, s);
        }
        float cw    = cosf(a + phase);
        float decay = expf(-0.5f * s);

        const int n = n0 + r;
        outE[n * KQ + kq] = sq * decay * cw;

        float d2  = decay * decay;
        float d4  = d2 * d2;
        float c2w = 2.0f * cw * cw - 1.0f;
        outC[n * KQ + kq] = coef * (0.5f + 0.5f * d4 * c2w);
    }
}

// ---------------------------------------------------------------------------
// Kernel 2: column sums of E_cos_sq
// ---------------------------------------------------------------------------
__global__ void diag_kernel(const float* __restrict__ out)
{
    const float* __restrict__ ecs = out + EPHI_SZ + G_SZ;
    const int tid  = threadIdx.x;
    const int base = blockIdx.x * 32;
    const int c    = tid & 31;
    const int g    = tid >> 5;

    float s = 0.0f;
    for (int n = g; n < N_PTS; n += 8)
        s += ecs[n * KQ + base + c];

    __shared__ float red[256];
    red[tid] = s;
    __syncthreads();
    if (tid < 32) {
        float tot = 0.0f;
#pragma unroll
        for (int gg = 0; gg < 8; ++gg) tot += red[gg * 32 + tid];
        g_diag[base + tid] = tot;
    }
}

// ---------------------------------------------------------------------------
// Kernel 3: transpose E_phi [N,KQ] f32 -> split bf16 hi/lo [KQ,N]
// ---------------------------------------------------------------------------
__global__ void splitT_kernel(const float* __restrict__ out)
{
    __shared__ float t[32][33];
    const int tx  = threadIdx.x;
    const int ty  = threadIdx.y;
    const int kq0 = blockIdx.x * 32;
    const int n0  = blockIdx.y * 32;

    const float* __restrict__ E = out;
#pragma unroll
    for (int i = 0; i < 4; ++i) {
        int r = ty + i * 8;
        t[r][tx] = E[(size_t)(n0 + r) * KQ + kq0 + tx];
    }
    __syncthreads();
#pragma unroll
    for (int i = 0; i < 4; ++i) {
        int rr = ty + i * 8;
        float f = t[tx][rr];
        __nv_bfloat16 h = __float2bfloat16(f);
        __nv_bfloat16 l = __float2bfloat16(f - __bfloat162float(h));
        size_t o = (size_t)(kq0 + rr) * N_PTS + n0 + tx;
        g_hi[o] = h;
        g_lo[o] = l;
    }
}

// ---------------------------------------------------------------------------
// Kernel 4: SYRK via split-bf16 mma.sync.
// 136 upper-triangular 64x64 tiles. 128 threads (4 warps, 2x2, 32x32 each).
// BK=64 (one 128B row segment per row), double-buffered cp.async.
// smem per stage: Ahi|Alo|Bhi|Blo each 64x128B = 8KB -> 32KB; 2 stages = 64KB
// ---------------------------------------------------------------------------
#define SB_AHI   0
#define SB_ALO   8192
#define SB_BHI   16384
#define SB_BLO   24576
#define SB_STAGE 32768
#define SMEM_SYRK (2 * SB_STAGE)
#define NCHUNK 128

__device__ __forceinline__ void load_chunk(uint32_t sbase, int stage, int chunk,
                                           int i0, int j0)
{
    const int t = threadIdx.x;
    const uint32_t ab = sbase + stage * SB_STAGE;
    const size_t koff = (size_t)chunk * 64;
#pragma unroll
    for (int it = 0; it < 4; ++it) {
        int v  = t + it * 128;           // 0..511 -> (row, 16B-seg)
        int r  = v >> 3;
        int sg = v & 7;
        uint32_t dst = (uint32_t)(r * 128 + ((sg ^ (r & 7)) * 16));
        const char* ah = (const char*)(g_hi + (size_t)(i0 + r) * N_PTS + koff) + sg * 16;
        const char* al = (const char*)(g_lo + (size_t)(i0 + r) * N_PTS + koff) + sg * 16;
        const char* bh = (const char*)(g_hi + (size_t)(j0 + r) * N_PTS + koff) + sg * 16;
        const char* bl = (const char*)(g_lo + (size_t)(j0 + r) * N_PTS + koff) + sg * 16;
        cp16(ab + SB_AHI + dst, ah);
        cp16(ab + SB_ALO + dst, al);
        cp16(ab + SB_BHI + dst, bh);
        cp16(ab + SB_BLO + dst, bl);
    }
}

__global__ void __launch_bounds__(128) syrk_mma_kernel(float* __restrict__ out)
{
    extern __shared__ __align__(1024) char smem[];
    const uint32_t sbase = smem_u32(smem);
    const int tid  = threadIdx.x;
    const int lane = tid & 31;
    const int wid  = tid >> 5;
    const int wm   = (wid & 1) * 32;     // warp m offset in tile
    const int wn   = (wid >> 1) * 32;    // warp n offset in tile

    // upper-triangular tile decode (16x16 grid of 64-wide tiles, ti <= tj)
    int b = blockIdx.x, ti = 0, rem = b;
    while (rem >= 16 - ti) { rem -= 16 - ti; ++ti; }
    const int tj = ti + rem;
    const int i0 = ti * 64;
    const int j0 = tj * 64;

    // per-lane ldmatrix addresses (hi buffers; lo = +8192; stage1 = +SB_STAGE)
    const int g  = lane >> 3;
    const int rr = lane & 7;
    uint32_t a_addr[2][4], b_addr[2][4];
#pragma unroll
    for (int mf = 0; mf < 2; ++mf)
#pragma unroll
        for (int ks = 0; ks < 4; ++ks) {
            int m  = wm + mf * 16 + rr + (g & 1) * 8;
            int cx = (g >> 1) + ks * 2;
            a_addr[mf][ks] = sbase + SB_AHI + m * 128 + ((cx ^ (m & 7)) * 16);
        }
#pragma unroll
    for (int nf2 = 0; nf2 < 2; ++nf2)
#pragma unroll
        for (int ks = 0; ks < 4; ++ks) {
            int n  = wn + nf2 * 16 + rr + (g >> 1) * 8;
            int cx = (g & 1) + ks * 2;
            b_addr[nf2][ks] = sbase + SB_BHI + n * 128 + ((cx ^ (n & 7)) * 16);
        }

    float acc[2][4][4];
#pragma unroll
    for (int mf = 0; mf < 2; ++mf)
#pragma unroll
        for (int nf = 0; nf < 4; ++nf)
#pragma unroll
            for (int r2 = 0; r2 < 4; ++r2) acc[mf][nf][r2] = 0.0f;

    load_chunk(sbase, 0, 0, i0, j0); cp_commit();
    load_chunk(sbase, 1, 1, i0, j0); cp_commit();

    for (int c = 0; c < NCHUNK; ++c) {
        if (c + 1 < NCHUNK) cp_wait<1>(); else cp_wait<0>();
        __syncthreads();
        const uint32_t so = (uint32_t)(c & 1) * SB_STAGE;

#pragma unroll
        for (int ks = 0; ks < 4; ++ks) {
            uint32_t ah[2][4], al[2][4], bh[2][4], bl[2][4];
            ldsm4(ah[0], a_addr[0][ks] + so);
            ldsm4(ah[1], a_addr[1][ks] + so);
            ldsm4(al[0], a_addr[0][ks] + so + 8192);
            ldsm4(al[1], a_addr[1][ks] + so + 8192);
            ldsm4(bh[0], b_addr[0][ks] + so);
            ldsm4(bh[1], b_addr[1][ks] + so);
            ldsm4(bl[0], b_addr[0][ks] + so + 8192);
            ldsm4(bl[1], b_addr[1][ks] + so + 8192);
#pragma unroll
            for (int mf = 0; mf < 2; ++mf)
#pragma unroll
                for (int nf = 0; nf < 4; ++nf) {
                    const int n2 = nf >> 1;
                    const int ns = (nf & 1) * 2;
                    mma_bf16(acc[mf][nf], ah[mf], bh[n2][ns], bh[n2][ns + 1]);
                    mma_bf16(acc[mf][nf], ah[mf], bl[n2][ns], bl[n2][ns + 1]);
                    mma_bf16(acc[mf][nf], al[mf], bh[n2][ns], bh[n2][ns + 1]);
                }
        }
        __syncthreads();
        if (c + 2 < NCHUNK) { load_chunk(sbase, c & 1, c + 2, i0, j0); cp_commit(); }
    }

    // epilogue: write G tile (upper)
    float* __restrict__ G = out + EPHI_SZ;
    const int r0   = lane >> 2;
    const int cpos = (lane & 3) * 2;
#pragma unroll
    for (int mf = 0; mf < 2; ++mf)
#pragma unroll
        for (int nf = 0; nf < 4; ++nf) {
            const int gi = i0 + wm + mf * 16 + r0;
            const int gj = j0 + wn + nf * 8 + cpos;
            G[(size_t)gi * KQ + gj]           = acc[mf][nf][0];
            G[(size_t)gi * KQ + gj + 1]       = acc[mf][nf][1];
            G[(size_t)(gi + 8) * KQ + gj]     = acc[mf][nf][2];
            G[(size_t)(gi + 8) * KQ + gj + 1] = acc[mf][nf][3];
        }
}

// ---------------------------------------------------------------------------
// Kernel 5: mirror strict-upper to strict-lower
// ---------------------------------------------------------------------------
__global__ void mirror_kernel(float* __restrict__ out)
{
    float* __restrict__ G = out + EPHI_SZ;
    int idx = blockIdx.x * blockDim.x + threadIdx.x;
    if (idx >= G_SZ) return;
    int i = idx >> 10;
    int j = idx & (KQ - 1);
    if (j > i) G[(size_t)j * KQ + i] = G[idx];
}

// ---------------------------------------------------------------------------
// Kernel 6: splice corrected diagonal
// ---------------------------------------------------------------------------
__global__ void diagfix_kernel(float* __restrict__ out)
{
    int i = blockIdx.x * blockDim.x + threadIdx.x;
    if (i < KQ) out[EPHI_SZ + (size_t)i * KQ + i] = g_diag[i];
}

// ---------------------------------------------------------------------------
extern "C" void kernel_launch(void* const* d_in, const int* in_sizes, int n_in,
                              void* d_out, int out_size)
{
    const float* X           = (const float*)d_in[0];
    const float* z           = (const float*)d_in[1];
    const float* weight      = (const float*)d_in[2];
    const float* mu          = (const float*)d_in[3];
    const float* stdv        = (const float*)d_in[4];
    const float* alpha       = (const float*)d_in[5];
    const float* var_mu_w    = (const float*)d_in[6];
    const float* var_sigma_w = (const float*)d_in[7];
    float* out = (float*)d_out;

    cudaFuncSetAttribute(syrk_mma_kernel,
                         cudaFuncAttributeMaxDynamicSharedMemorySize, SMEM_SYRK);

    precompute_kernel<<<32, 256>>>(z, mu, stdv, var_mu_w, var_sigma_w);

    dim3 egrid(KQ / 256, N_PTS / 32);
    ephi_kernel<<<egrid, 256>>>(X, weight, alpha, out);

    diag_kernel<<<KQ / 32, 256>>>(out);

    dim3 tgrid(KQ / 32, N_PTS / 32);
    splitT_kernel<<<tgrid, dim3(32, 8)>>>(out);

    syrk_mma_kernel<<<136, 128, SMEM_SYRK>>>(out);

    mirror_kernel<<<G_SZ / 256, 256>>>(out);

    diagfix_kernel<<<4, 256>>>(out);
}

// round 4
// speedup vs baseline: 2.5963x; 1.1005x over previous
#include <cuda_runtime.h>
#include <cuda_bf16.h>
#include <math.h>
#include <stdint.h>

#define N_PTS   8192
#define D_DIM   8
#define K_DIM   64
#define Q_DIM   16
#define KQ      1024
#define TWO_PI  6.283185307179586f

#define EPHI_SZ (N_PTS * KQ)    // 8388608
#define G_SZ    (KQ * KQ)       // 1048576
// d_out layout: [E_phi (N,KQ) | G (KQ,KQ) | E_cos_sq (N,KQ)]

// -------- device scratch --------
__device__ float g_Ew[D_DIM * KQ];
__device__ float g_C [D_DIM * KQ];
__device__ float g_zs[D_DIM * KQ];
__device__ float g_diag[KQ];
__device__ float g_dpart[256 * KQ];          // per-(n-block) partial col sums
// transposed split E_phi: [KQ][N_PTS] bf16, n contiguous
__device__ __nv_bfloat16 g_hi[(size_t)KQ * N_PTS];
__device__ __nv_bfloat16 g_lo[(size_t)KQ * N_PTS];

// ---------------------------------------------------------------------------
// helpers (sm_80-level PTX only: cp.async, ldmatrix, mma.sync)
// ---------------------------------------------------------------------------
__device__ __forceinline__ uint32_t smem_u32(const void* p) {
    uint32_t a;
    asm("{ .reg .u64 t; cvta.to.shared.u64 t, %1; cvt.u32.u64 %0, t; }"
        : "=r"(a) : "l"(p));
    return a;
}
__device__ __forceinline__ void cp16(uint32_t dst, const void* src) {
    asm volatile("cp.async.cg.shared.global [%0], [%1], 16;"
                 :: "r"(dst), "l"(src));
}
__device__ __forceinline__ void cp_commit() {
    asm volatile("cp.async.commit_group;" ::: "memory");
}
template <int N>
__device__ __forceinline__ void cp_wait() {
    asm volatile("cp.async.wait_group %0;" :: "n"(N) : "memory");
}
__device__ __forceinline__ void ldsm4(uint32_t* r, uint32_t addr) {
    asm volatile("ldmatrix.sync.aligned.m8n8.x4.shared.b16 {%0,%1,%2,%3}, [%4];"
                 : "=r"(r[0]), "=r"(r[1]), "=r"(r[2]), "=r"(r[3]) : "r"(addr));
}
__device__ __forceinline__ void mma_bf16(float* c, const uint32_t* a,
                                         uint32_t b0, uint32_t b1) {
    asm volatile(
        "mma.sync.aligned.m16n8k16.row.col.f32.bf16.bf16.f32 "
        "{%0,%1,%2,%3}, {%4,%5,%6,%7}, {%8,%9}, {%0,%1,%2,%3};"
        : "+f"(c[0]), "+f"(c[1]), "+f"(c[2]), "+f"(c[3])
        : "r"(a[0]), "r"(a[1]), "r"(a[2]), "r"(a[3]), "r"(b0), "r"(b1));
}

// ---------------------------------------------------------------------------
// Kernel 0: precompute coefficient tables
// ---------------------------------------------------------------------------
__global__ void precompute_kernel(const float* __restrict__ z,
                                  const float* __restrict__ mu,
                                  const float* __restrict__ stdv,
                                  const float* __restrict__ var_mu_w,
                                  const float* __restrict__ var_sigma_w)
{
    int idx = blockIdx.x * blockDim.x + threadIdx.x;
    if (idx >= D_DIM * KQ) return;
    int d  = idx >> 10;
    int kq = idx & (KQ - 1);
    int q  = kq & (Q_DIM - 1);

    float mean_p = 1.0f / (mu[d * Q_DIM + q] + 1e-8f);
    float std_p  = 1.0f / (TWO_PI * stdv[d * Q_DIM + q] + 1e-8f);

    g_Ew[idx] = mean_p + std_p * var_mu_w[idx];
    g_C [idx] = std_p * std_p * var_sigma_w[idx];
    g_zs[idx] = TWO_PI * z[idx];
}

// ---------------------------------------------------------------------------
// Kernel 1: fused — E_phi, E_cos_sq, split-bf16 transposed hi/lo, diag partials
// grid (4, 256), block 256. Block = 256 kq x 32 n.
// ---------------------------------------------------------------------------
__global__ void __launch_bounds__(256) ephi_kernel(const float* __restrict__ X,
                            const float* __restrict__ weight,
                            const float* __restrict__ alpha,
                            float* __restrict__ out)
{
    const int tid = threadIdx.x;
    const int kq0 = blockIdx.x * 256;
    const int kq  = kq0 + tid;
    const int n0  = blockIdx.y * 32;

    __shared__ float Xs[256];
    __shared__ __nv_bfloat16 s_hi[256][34];   // pad 34 -> conflict-light
    __shared__ __nv_bfloat16 s_lo[256][34];

    Xs[tid] = TWO_PI * X[n0 * D_DIM + tid];   // 32 rows x 8 dims
    __syncthreads();

    float ew[D_DIM], cc[D_DIM], zz[D_DIM];
#pragma unroll
    for (int d = 0; d < D_DIM; ++d) {
        ew[d] = g_Ew[d * KQ + kq];
        cc[d] = g_C [d * KQ + kq];
        zz[d] = g_zs[d * KQ + kq];
    }
    const int   q    = kq & (Q_DIM - 1);
    const float a    = alpha[kq];
    const float coef = 2.0f * weight[q] * (1.0f / (float)K_DIM);
    const float sq   = sqrtf(coef);

    float* __restrict__ outE = out;
    float* __restrict__ outC = out + EPHI_SZ + G_SZ;

    float dsum = 0.0f;
#pragma unroll 4
    for (int r = 0; r < 32; ++r) {
        float phase = 0.0f, s = 0.0f;
#pragma unroll
        for (int d = 0; d < D_DIM; ++d) {
            float xb = Xs[r * D_DIM + d] - zz[d];
            phase = fmaf(xb, ew[d], phase);
            s     = fmaf(cc[d], xb * xb, s);
        }
        float cw    = cosf(a + phase);
        float decay = expf(-0.5f * s);

        const int n = n0 + r;
        float E = sq * decay * cw;
        outE[n * KQ + kq] = E;

        float d2  = decay * decay;
        float d4  = d2 * d2;
        float c2w = 2.0f * cw * cw - 1.0f;
        float ecs = coef * (0.5f + 0.5f * d4 * c2w);
        outC[n * KQ + kq] = ecs;
        dsum += ecs;

        __nv_bfloat16 h = __float2bfloat16(E);
        s_hi[tid][r] = h;
        s_lo[tid][r] = __float2bfloat16(E - __bfloat162float(h));
    }
    g_dpart[blockIdx.y * KQ + kq] = dsum;
    __syncthreads();

    // transposed write: g_hi/g_lo [kq][n], 2 bf16 per u32 store
    uint32_t* __restrict__ H = (uint32_t*)g_hi;
    uint32_t* __restrict__ L = (uint32_t*)g_lo;
#pragma unroll
    for (int i = 0; i < 16; ++i) {
        int v   = tid + i * 256;
        int row = v >> 4;
        int seg = v & 15;
        uint32_t h2 = *(const uint32_t*)&s_hi[row][seg * 2];
        uint32_t l2 = *(const uint32_t*)&s_lo[row][seg * 2];
        size_t o = ((size_t)(kq0 + row) * N_PTS + n0) / 2 + seg;
        H[o] = h2;
        L[o] = l2;
    }
}

// ---------------------------------------------------------------------------
// Kernel 2: reduce diag partials (256 partials per kq)
// ---------------------------------------------------------------------------
__global__ void diag_reduce_kernel()
{
    int kq = blockIdx.x * 256 + threadIdx.x;
    float s = 0.0f;
    for (int p = 0; p < 256; ++p)
        s += g_dpart[p * KQ + kq];
    g_diag[kq] = s;
}

// ---------------------------------------------------------------------------
// Kernel 3: SYRK via split-bf16 mma.sync.
// 136 upper-triangular 64x64 tiles. 256 threads (8 warps, 2x4 grid, 32x16
// warp tile). BK=64, 3-stage cp.async pipeline.
// smem per stage: Ahi|Alo|Bhi|Blo each 64x128B = 8KB -> 32KB; 3 stages = 96KB
// ---------------------------------------------------------------------------
#define SB_AHI   0
#define SB_ALO   8192
#define SB_BHI   16384
#define SB_BLO   24576
#define SB_STAGE 32768
#define NSTAGE   3
#define SMEM_SYRK (NSTAGE * SB_STAGE)
#define NCHUNK 128

__device__ __forceinline__ void load_chunk(uint32_t sbase, int stage, int chunk,
                                           int i0, int j0)
{
    const int t = threadIdx.x;
    const uint32_t ab = sbase + stage * SB_STAGE;
    const size_t koff = (size_t)chunk * 64;
#pragma unroll
    for (int it = 0; it < 8; ++it) {
        const int buf = it >> 1;                 // 0:AHI 1:ALO 2:BHI 3:BLO
        const int w   = t + (it & 1) * 256;      // 0..511
        const int r   = w >> 3;
        const int sg  = w & 7;
        const uint32_t dst = ab + (uint32_t)(buf * 8192)
                           + (uint32_t)(r * 128 + ((sg ^ (r & 7)) * 16));
        const int row = (buf < 2 ? i0 : j0) + r;
        const __nv_bfloat16* base = (buf & 1) ? g_lo : g_hi;
        const char* src = (const char*)(base + (size_t)row * N_PTS + koff) + sg * 16;
        cp16(dst, src);
    }
}

__global__ void __launch_bounds__(256) syrk_mma_kernel(float* __restrict__ out)
{
    extern __shared__ __align__(1024) char smem[];
    const uint32_t sbase = smem_u32(smem);
    const int tid  = threadIdx.x;
    const int lane = tid & 31;
    const int wid  = tid >> 5;
    const int wm   = (wid & 1) * 32;     // warp m offset (0/32)
    const int wn   = (wid >> 1) * 16;    // warp n offset (0/16/32/48)

    // upper-triangular tile decode (16x16 grid of 64-wide tiles, ti <= tj)
    int b = blockIdx.x, ti = 0, rem = b;
    while (rem >= 16 - ti) { rem -= 16 - ti; ++ti; }
    const int tj = ti + rem;
    const int i0 = ti * 64;
    const int j0 = tj * 64;

    // per-lane ldmatrix addresses (hi buffers; lo = +8192)
    const int g  = lane >> 3;
    const int rr = lane & 7;
    uint32_t a_addr[2][4], b_addr[4];
#pragma unroll
    for (int mf = 0; mf < 2; ++mf)
#pragma unroll
        for (int ks = 0; ks < 4; ++ks) {
            int m  = wm + mf * 16 + rr + (g & 1) * 8;
            int cx = (g >> 1) + ks * 2;
            a_addr[mf][ks] = sbase + SB_AHI + m * 128 + ((cx ^ (m & 7)) * 16);
        }
#pragma unroll
    for (int ks = 0; ks < 4; ++ks) {
        int n  = wn + rr + (g >> 1) * 8;
        int cx = (g & 1) + ks * 2;
        b_addr[ks] = sbase + SB_BHI + n * 128 + ((cx ^ (n & 7)) * 16);
    }

    float acc[2][2][4];
#pragma unroll
    for (int mf = 0; mf < 2; ++mf)
#pragma unroll
        for (int nf = 0; nf < 2; ++nf)
#pragma unroll
            for (int r2 = 0; r2 < 4; ++r2) acc[mf][nf][r2] = 0.0f;

    load_chunk(sbase, 0, 0, i0, j0); cp_commit();
    load_chunk(sbase, 1, 1, i0, j0); cp_commit();
    load_chunk(sbase, 2, 2, i0, j0); cp_commit();

    for (int c = 0; c < NCHUNK; ++c) {
        if (c < NCHUNK - 2)      cp_wait<2>();
        else if (c == NCHUNK - 2) cp_wait<1>();
        else                      cp_wait<0>();
        __syncthreads();

        const int s = c % NSTAGE;
        const uint32_t so = (uint32_t)s * SB_STAGE;

#pragma unroll
        for (int ks = 0; ks < 4; ++ks) {
            uint32_t ah[2][4], al[2][4], bh[4], bl[4];
            ldsm4(ah[0], a_addr[0][ks] + so);
            ldsm4(ah[1], a_addr[1][ks] + so);
            ldsm4(al[0], a_addr[0][ks] + so + 8192);
            ldsm4(al[1], a_addr[1][ks] + so + 8192);
            ldsm4(bh,    b_addr[ks] + so);
            ldsm4(bl,    b_addr[ks] + so + 8192);
#pragma unroll
            for (int mf = 0; mf < 2; ++mf)
#pragma unroll
                for (int nf = 0; nf < 2; ++nf) {
                    mma_bf16(acc[mf][nf], ah[mf], bh[nf * 2], bh[nf * 2 + 1]);
                    mma_bf16(acc[mf][nf], ah[mf], bl[nf * 2], bl[nf * 2 + 1]);
                    mma_bf16(acc[mf][nf], al[mf], bh[nf * 2], bh[nf * 2 + 1]);
                }
        }
        __syncthreads();
        if (c + NSTAGE < NCHUNK) {
            load_chunk(sbase, s, c + NSTAGE, i0, j0);
            cp_commit();
        }
    }

    // epilogue: write G tile (upper)
    float* __restrict__ G = out + EPHI_SZ;
    const int r0   = lane >> 2;
    const int cpos = (lane & 3) * 2;
#pragma unroll
    for (int mf = 0; mf < 2; ++mf)
#pragma unroll
        for (int nf = 0; nf < 2; ++nf) {
            const int gi = i0 + wm + mf * 16 + r0;
            const int gj = j0 + wn + nf * 8 + cpos;
            G[(size_t)gi * KQ + gj]           = acc[mf][nf][0];
            G[(size_t)gi * KQ + gj + 1]       = acc[mf][nf][1];
            G[(size_t)(gi + 8) * KQ + gj]     = acc[mf][nf][2];
            G[(size_t)(gi + 8) * KQ + gj + 1] = acc[mf][nf][3];
        }
}

// ---------------------------------------------------------------------------
// Kernel 4: mirror strict-upper to strict-lower
// ---------------------------------------------------------------------------
__global__ void mirror_kernel(float* __restrict__ out)
{
    float* __restrict__ G = out + EPHI_SZ;
    int idx = blockIdx.x * blockDim.x + threadIdx.x;
    if (idx >= G_SZ) return;
    int i = idx >> 10;
    int j = idx & (KQ - 1);
    if (j > i) G[(size_t)j * KQ + i] = G[idx];
}

// ---------------------------------------------------------------------------
// Kernel 5: splice corrected diagonal
// ---------------------------------------------------------------------------
__global__ void diagfix_kernel(float* __restrict__ out)
{
    int i = blockIdx.x * blockDim.x + threadIdx.x;
    if (i < KQ) out[EPHI_SZ + (size_t)i * KQ + i] = g_diag[i];
}

// ---------------------------------------------------------------------------
extern "C" void kernel_launch(void* const* d_in, const int* in_sizes, int n_in,
                              void* d_out, int out_size)
{
    const float* X           = (const float*)d_in[0];
    const float* z           = (const float*)d_in[1];
    const float* weight      = (const float*)d_in[2];
    const float* mu          = (const float*)d_in[3];
    const float* stdv        = (const float*)d_in[4];
    const float* alpha       = (const float*)d_in[5];
    const float* var_mu_w    = (const float*)d_in[6];
    const float* var_sigma_w = (const float*)d_in[7];
    float* out = (float*)d_out;

    cudaFuncSetAttribute(syrk_mma_kernel,
                         cudaFuncAttributeMaxDynamicSharedMemorySize, SMEM_SYRK);

    precompute_kernel<<<32, 256>>>(z, mu, stdv, var_mu_w, var_sigma_w);

    dim3 egrid(KQ / 256, N_PTS / 32);
    ephi_kernel<<<egrid, 256>>>(X, weight, alpha, out);

    diag_reduce_kernel<<<4, 256>>>();

    syrk_mma_kernel<<<136, 256, SMEM_SYRK>>>(out);

    mirror_kernel<<<G_SZ / 256, 256>>>(out);

    diagfix_kernel<<<4, 256>>>(out);
}

// round 5
// speedup vs baseline: 3.1847x; 1.2267x over previous
#include <cuda_runtime.h>
#include <cuda_bf16.h>
#include <math.h>
#include <stdint.h>

#define N_PTS   8192
#define D_DIM   8
#define K_DIM   64
#define Q_DIM   16
#define KQ      1024
#define TWO_PI  6.283185307179586f

#define EPHI_SZ (N_PTS * KQ)    // 8388608
#define G_SZ    (KQ * KQ)       // 1048576
// d_out layout: [E_phi (N,KQ) | G (KQ,KQ) | E_cos_sq (N,KQ)]

// -------- device scratch --------
__device__ float g_Ew[D_DIM * KQ];
__device__ float g_C [D_DIM * KQ];
__device__ float g_zs[D_DIM * KQ];
__device__ float g_diag[KQ];
__device__ float g_dpart[256 * KQ];
__device__ __nv_bfloat16 g_hi[(size_t)KQ * N_PTS];
__device__ __nv_bfloat16 g_lo[(size_t)KQ * N_PTS];

// ---------------------------------------------------------------------------
// helpers
// ---------------------------------------------------------------------------
__device__ __forceinline__ uint32_t smem_u32(const void* p) {
    uint32_t a;
    asm("{ .reg .u64 t; cvta.to.shared.u64 t, %1; cvt.u32.u64 %0, t; }"
        : "=r"(a) : "l"(p));
    return a;
}
__device__ __forceinline__ void cp16(uint32_t dst, const void* src) {
    asm volatile("cp.async.cg.shared.global [%0], [%1], 16;"
                 :: "r"(dst), "l"(src));
}
__device__ __forceinline__ void cp_commit() {
    asm volatile("cp.async.commit_group;" ::: "memory");
}
template <int N>
__device__ __forceinline__ void cp_wait() {
    asm volatile("cp.async.wait_group %0;" :: "n"(N) : "memory");
}
__device__ __forceinline__ void ldsm4(uint32_t* r, uint32_t addr) {
    asm volatile("ldmatrix.sync.aligned.m8n8.x4.shared.b16 {%0,%1,%2,%3}, [%4];"
                 : "=r"(r[0]), "=r"(r[1]), "=r"(r[2]), "=r"(r[3]) : "r"(addr));
}
__device__ __forceinline__ void mma_bf16(float* c, const uint32_t* a,
                                         uint32_t b0, uint32_t b1) {
    asm volatile(
        "mma.sync.aligned.m16n8k16.row.col.f32.bf16.bf16.f32 "
        "{%0,%1,%2,%3}, {%4,%5,%6,%7}, {%8,%9}, {%0,%1,%2,%3};"
        : "+f"(c[0]), "+f"(c[1]), "+f"(c[2]), "+f"(c[3])
        : "r"(a[0]), "r"(a[1]), "r"(a[2]), "r"(a[3]), "r"(b0), "r"(b1));
}

// ---------------------------------------------------------------------------
// Kernel 0: precompute coefficient tables
// ---------------------------------------------------------------------------
__global__ void precompute_kernel(const float* __restrict__ z,
                                  const float* __restrict__ mu,
                                  const float* __restrict__ stdv,
                                  const float* __restrict__ var_mu_w,
                                  const float* __restrict__ var_sigma_w)
{
    int idx = blockIdx.x * blockDim.x + threadIdx.x;
    if (idx >= D_DIM * KQ) return;
    int d  = idx >> 10;
    int kq = idx & (KQ - 1);
    int q  = kq & (Q_DIM - 1);

    float mean_p = 1.0f / (mu[d * Q_DIM + q] + 1e-8f);
    float std_p  = 1.0f / (TWO_PI * stdv[d * Q_DIM + q] + 1e-8f);

    g_Ew[idx] = mean_p + std_p * var_mu_w[idx];
    g_C [idx] = std_p * std_p * var_sigma_w[idx];
    g_zs[idx] = TWO_PI * z[idx];
}

// ---------------------------------------------------------------------------
// Kernel 1: fused E_phi, E_cos_sq, split-bf16 transposed hi/lo, diag partials
// ---------------------------------------------------------------------------
__global__ void __launch_bounds__(256) ephi_kernel(const float* __restrict__ X,
                            const float* __restrict__ weight,
                            const float* __restrict__ alpha,
                            float* __restrict__ out)
{
    const int tid = threadIdx.x;
    const int kq0 = blockIdx.x * 256;
    const int kq  = kq0 + tid;
    const int n0  = blockIdx.y * 32;

    __shared__ float Xs[256];
    __shared__ __nv_bfloat16 s_hi[256][34];
    __shared__ __nv_bfloat16 s_lo[256][34];

    Xs[tid] = TWO_PI * X[n0 * D_DIM + tid];
    __syncthreads();

    float ew[D_DIM], cc[D_DIM], zz[D_DIM];
#pragma unroll
    for (int d = 0; d < D_DIM; ++d) {
        ew[d] = g_Ew[d * KQ + kq];
        cc[d] = g_C [d * KQ + kq];
        zz[d] = g_zs[d * KQ + kq];
    }
    const int   q    = kq & (Q_DIM - 1);
    const float a    = alpha[kq];
    const float coef = 2.0f * weight[q] * (1.0f / (float)K_DIM);
    const float sq   = sqrtf(coef);

    float* __restrict__ outE = out;
    float* __restrict__ outC = out + EPHI_SZ + G_SZ;

    float dsum = 0.0f;
#pragma unroll 4
    for (int r = 0; r < 32; ++r) {
        float phase = 0.0f, s = 0.0f;
#pragma unroll
        for (int d = 0; d < D_DIM; ++d) {
            float xb = Xs[r * D_DIM + d] - zz[d];
            phase = fmaf(xb, ew[d], phase);
            s     = fmaf(cc[d], xb * xb, s);
        }
        float cw    = cosf(a + phase);
        float decay = expf(-0.5f * s);

        const int n = n0 + r;
        float E = sq * decay * cw;
        outE[n * KQ + kq] = E;

        float d2  = decay * decay;
        float d4  = d2 * d2;
        float c2w = 2.0f * cw * cw - 1.0f;
        float ecs = coef * (0.5f + 0.5f * d4 * c2w);
        outC[n * KQ + kq] = ecs;
        dsum += ecs;

        __nv_bfloat16 h = __float2bfloat16(E);
        s_hi[tid][r] = h;
        s_lo[tid][r] = __float2bfloat16(E - __bfloat162float(h));
    }
    g_dpart[blockIdx.y * KQ + kq] = dsum;
    __syncthreads();

    uint32_t* __restrict__ H = (uint32_t*)g_hi;
    uint32_t* __restrict__ L = (uint32_t*)g_lo;
#pragma unroll
    for (int i = 0; i < 16; ++i) {
        int v   = tid + i * 256;
        int row = v >> 4;
        int seg = v & 15;
        uint32_t h2 = *(const uint32_t*)&s_hi[row][seg * 2];
        uint32_t l2 = *(const uint32_t*)&s_lo[row][seg * 2];
        size_t o = ((size_t)(kq0 + row) * N_PTS + n0) / 2 + seg;
        H[o] = h2;
        L[o] = l2;
    }
}

// ---------------------------------------------------------------------------
// Kernel 2: reduce diag partials
// ---------------------------------------------------------------------------
__global__ void diag_reduce_kernel()
{
    int kq = blockIdx.x * 256 + threadIdx.x;
    float s = 0.0f;
    for (int p = 0; p < 256; ++p)
        s += g_dpart[p * KQ + kq];
    g_diag[kq] = s;
}

// ---------------------------------------------------------------------------
// Kernel 3: SYRK via split-bf16 mma.sync, k-split 2-way, 32x32 warp tiles.
// 136 upper-triangular 64x64 tiles. 256 threads.
// Superchunk = 128 k values; 64 superchunks; 3-stage pipeline.
// Stage: AHI|ALO|BHI|BLO each 64 rows x 256B = 16KB -> 64KB; 3 stages = 192KB.
// Warps 0-3 (2x2) handle k 0-63 of the superchunk, warps 4-7 handle k 64-127.
// Epilogue: cross-set smem reduce; writes tile + mirror + spliced diagonal.
// ---------------------------------------------------------------------------
#define SB_AHI   0
#define SB_ALO   16384
#define SB_BHI   32768
#define SB_BLO   49152
#define SB_STAGE 65536
#define NSTAGE   3
#define SMEM_SYRK (NSTAGE * SB_STAGE)
#define NSC 64

__device__ __forceinline__ void load_chunk(uint32_t sbase, int stage, int sc,
                                           int i0, int j0)
{
    const int t = threadIdx.x;
    const uint32_t ab = sbase + stage * SB_STAGE;
    const size_t koff = (size_t)sc * 128;
#pragma unroll
    for (int it = 0; it < 16; ++it) {
        const int v   = t + it * 256;          // 0..4095
        const int buf = v >> 10;               // 0:AHI 1:ALO 2:BHI 3:BLO
        const int r   = (v >> 4) & 63;
        const int s   = v & 15;                // 16B segment along k
        const int half = s >> 3;
        const int sg   = s & 7;
        const uint32_t dst = ab + (uint32_t)(buf << 14)
                           + (uint32_t)(r * 256 + half * 128
                                        + ((sg ^ (r & 7)) << 4));
        const int row = (buf < 2 ? i0 : j0) + r;
        const __nv_bfloat16* base = (buf & 1) ? g_lo : g_hi;
        const char* src = (const char*)(base + (size_t)row * N_PTS + koff)
                        + s * 16;
        cp16(dst, src);
    }
}

__global__ void __launch_bounds__(256, 1) syrk_mma_kernel(float* __restrict__ out)
{
    extern __shared__ __align__(1024) char smem[];
    const uint32_t sbase = smem_u32(smem);
    const int tid  = threadIdx.x;
    const int lane = tid & 31;
    const int wid  = tid >> 5;
    const int wset = wid >> 2;                 // 0: k 0-63, 1: k 64-127
    const int wli  = wid & 3;                  // warp within set (2x2)
    const int wm   = (wli & 1) * 32;
    const int wn   = (wli >> 1) * 32;
    const uint32_t halfB = (uint32_t)wset * 128;

    int b = blockIdx.x, ti = 0, rem = b;
    while (rem >= 16 - ti) { rem -= 16 - ti; ++ti; }
    const int tj = ti + rem;
    const int i0 = ti * 64;
    const int j0 = tj * 64;

    const int g  = lane >> 3;
    const int rr = lane & 7;
    uint32_t a_addr[2][4], b_addr[2][4];
#pragma unroll
    for (int mf = 0; mf < 2; ++mf)
#pragma unroll
        for (int ks = 0; ks < 4; ++ks) {
            int m  = wm + mf * 16 + rr + (g & 1) * 8;
            int cx = (g >> 1) + ks * 2;
            a_addr[mf][ks] = sbase + SB_AHI + m * 256 + halfB
                           + ((cx ^ (m & 7)) << 4);
        }
#pragma unroll
    for (int nf2 = 0; nf2 < 2; ++nf2)
#pragma unroll
        for (int ks = 0; ks < 4; ++ks) {
            int n  = wn + nf2 * 16 + rr + (g >> 1) * 8;
            int cx = (g & 1) + ks * 2;
            b_addr[nf2][ks] = sbase + SB_BHI + n * 256 + halfB
                            + ((cx ^ (n & 7)) << 4);
        }

    float acc[2][4][4];
#pragma unroll
    for (int mf = 0; mf < 2; ++mf)
#pragma unroll
        for (int nf = 0; nf < 4; ++nf)
#pragma unroll
            for (int r2 = 0; r2 < 4; ++r2) acc[mf][nf][r2] = 0.0f;

    load_chunk(sbase, 0, 0, i0, j0); cp_commit();
    load_chunk(sbase, 1, 1, i0, j0); cp_commit();
    load_chunk(sbase, 2, 2, i0, j0); cp_commit();

    for (int sc = 0; sc < NSC; ++sc) {
        if (sc <= NSC - 3)      cp_wait<2>();
        else if (sc == NSC - 2) cp_wait<1>();
        else                    cp_wait<0>();
        __syncthreads();

        const int s = sc % NSTAGE;
        const uint32_t so = (uint32_t)s * SB_STAGE;

#pragma unroll
        for (int ks = 0; ks < 4; ++ks) {
            uint32_t ah[2][4], al[2][4], bh[2][4], bl[2][4];
            ldsm4(ah[0], a_addr[0][ks] + so);
            ldsm4(ah[1], a_addr[1][ks] + so);
            ldsm4(al[0], a_addr[0][ks] + so + 16384);
            ldsm4(al[1], a_addr[1][ks] + so + 16384);
            ldsm4(bh[0], b_addr[0][ks] + so);
            ldsm4(bh[1], b_addr[1][ks] + so);
            ldsm4(bl[0], b_addr[0][ks] + so + 16384);
            ldsm4(bl[1], b_addr[1][ks] + so + 16384);
            // chain-outer order: same-acc writes 8 mmas apart
#pragma unroll
            for (int mf = 0; mf < 2; ++mf)
#pragma unroll
                for (int nf = 0; nf < 4; ++nf)
                    mma_bf16(acc[mf][nf], ah[mf],
                             bh[nf >> 1][(nf & 1) * 2], bh[nf >> 1][(nf & 1) * 2 + 1]);
#pragma unroll
            for (int mf = 0; mf < 2; ++mf)
#pragma unroll
                for (int nf = 0; nf < 4; ++nf)
                    mma_bf16(acc[mf][nf], ah[mf],
                             bl[nf >> 1][(nf & 1) * 2], bl[nf >> 1][(nf & 1) * 2 + 1]);
#pragma unroll
            for (int mf = 0; mf < 2; ++mf)
#pragma unroll
                for (int nf = 0; nf < 4; ++nf)
                    mma_bf16(acc[mf][nf], al[mf],
                             bh[nf >> 1][(nf & 1) * 2], bh[nf >> 1][(nf & 1) * 2 + 1]);
        }
        __syncthreads();
        if (sc + NSTAGE < NSC) {
            load_chunk(sbase, s, sc + NSTAGE, i0, j0);
            cp_commit();
        }
    }

    // ---- epilogue: cross-set reduction + write (tile, mirror, diag) ----
    float (*red)[65] = (float (*)[65])smem;    // 64x65 f32, reuses stage 0
    const int r0   = lane >> 2;
    const int cpos = (lane & 3) * 2;

    if (wset == 1) {
#pragma unroll
        for (int mf = 0; mf < 2; ++mf)
#pragma unroll
            for (int nf = 0; nf < 4; ++nf) {
                const int rl = wm + mf * 16 + r0;
                const int cl = wn + nf * 8 + cpos;
                red[rl][cl]         = acc[mf][nf][0];
                red[rl][cl + 1]     = acc[mf][nf][1];
                red[rl + 8][cl]     = acc[mf][nf][2];
                red[rl + 8][cl + 1] = acc[mf][nf][3];
            }
    }
    __syncthreads();

    if (wset == 0) {
        float* __restrict__ G = out + EPHI_SZ;
#pragma unroll
        for (int mf = 0; mf < 2; ++mf)
#pragma unroll
            for (int nf = 0; nf < 4; ++nf)
#pragma unroll
                for (int r2 = 0; r2 < 4; ++r2) {
                    const int rl = wm + mf * 16 + r0 + (r2 >> 1) * 8;
                    const int cl = wn + nf * 8 + cpos + (r2 & 1);
                    const int gi = i0 + rl;
                    const int gj = j0 + cl;
                    float val = acc[mf][nf][r2] + red[rl][cl];
                    if (gi == gj) val = g_diag[gi];
                    G[(size_t)gi * KQ + gj] = val;
                    G[(size_t)gj * KQ + gi] = val;
                }
    }
}

// ---------------------------------------------------------------------------
extern "C" void kernel_launch(void* const* d_in, const int* in_sizes, int n_in,
                              void* d_out, int out_size)
{
    const float* X           = (const float*)d_in[0];
    const float* z           = (const float*)d_in[1];
    const float* weight      = (const float*)d_in[2];
    const float* mu          = (const float*)d_in[3];
    const float* stdv        = (const float*)d_in[4];
    const float* alpha       = (const float*)d_in[5];
    const float* var_mu_w    = (const float*)d_in[6];
    const float* var_sigma_w = (const float*)d_in[7];
    float* out = (float*)d_out;

    cudaFuncSetAttribute(syrk_mma_kernel,
                         cudaFuncAttributeMaxDynamicSharedMemorySize, SMEM_SYRK);

    precompute_kernel<<<32, 256>>>(z, mu, stdv, var_mu_w, var_sigma_w);

    dim3 egrid(KQ / 256, N_PTS / 32);
    ephi_kernel<<<egrid, 256>>>(X, weight, alpha, out);

    diag_reduce_kernel<<<4, 256>>>();

    syrk_mma_kernel<<<136, 256, SMEM_SYRK>>>(out);
}